// round 4
// baseline (speedup 1.0000x reference)
#include <cuda_runtime.h>
#include <cuda_bf16.h>
#include <cstdint>

#define N_TOK 10368
#define CDIM  256
#define HDIM  128
#define NCHUNK 81
#define STR   136          // padded smem row length in bf16 elems (272B, conflict-free)
#define TILE_B (128 * STR * 2)   // 34816 bytes per 128x128 bf16 tile
#define CPAD  132          // padded C staging row (floats)

// ---------------- scratch (no cudaMalloc allowed) ----------------
__device__ float g_featT[(size_t)N_TOK * CDIM];   // featT[n][k]
__device__ float g_FiT [(size_t)N_TOK * HDIM];    // FiT[n][p]
__device__ float g_Fj  [(size_t)HDIM * N_TOK];    // Fj[p][n]
__device__ float g_Gpart[(size_t)NCHUNK * HDIM * CDIM];
__device__ float g_GT  [(size_t)CDIM * HDIM];     // GT[q][p] = G[p][q]/N

// ---------------- helpers ----------------
__device__ __forceinline__ uint32_t smem_u32(const void* p) {
    uint32_t a;
    asm("{ .reg .u64 t; cvta.to.shared.u64 t, %1; cvt.u32.u64 %0, t; }" : "=r"(a) : "l"(p));
    return a;
}
__device__ __forceinline__ void ldsm4(uint32_t* r, uint32_t a) {
    asm volatile("ldmatrix.sync.aligned.m8n8.x4.shared.b16 {%0,%1,%2,%3}, [%4];"
                 : "=r"(r[0]), "=r"(r[1]), "=r"(r[2]), "=r"(r[3]) : "r"(a));
}
__device__ __forceinline__ void mma_bf16(float* d, const uint32_t* a, const uint32_t* b) {
    asm volatile("mma.sync.aligned.m16n8k16.row.col.f32.bf16.bf16.f32 "
                 "{%0,%1,%2,%3}, {%4,%5,%6,%7}, {%8,%9}, {%0,%1,%2,%3};"
                 : "+f"(d[0]), "+f"(d[1]), "+f"(d[2]), "+f"(d[3])
                 : "r"(a[0]), "r"(a[1]), "r"(a[2]), "r"(a[3]), "r"(b[0]), "r"(b[1]));
}

// Stage a [ROWS x 128] fp32 tile (leading dim ld) into hi/lo bf16 padded tiles.
template<int ROWS>
__device__ __forceinline__ void stage(uint32_t dhi, uint32_t dlo,
                                      const float* __restrict__ src, int ld, int tid)
{
    for (int i = tid; i < ROWS * 32; i += 256) {
        int r = i >> 5, kk = (i & 31) << 2;
        float4 v = *(const float4*)(src + (size_t)r * ld + kk);
        __nv_bfloat16 h0 = __float2bfloat16_rn(v.x), h1 = __float2bfloat16_rn(v.y),
                      h2 = __float2bfloat16_rn(v.z), h3 = __float2bfloat16_rn(v.w);
        float l0 = v.x - __bfloat162float(h0), l1 = v.y - __bfloat162float(h1),
              l2 = v.z - __bfloat162float(h2), l3 = v.w - __bfloat162float(h3);
        uint32_t hA = (uint32_t)__bfloat16_as_ushort(h0) | ((uint32_t)__bfloat16_as_ushort(h1) << 16);
        uint32_t hB = (uint32_t)__bfloat16_as_ushort(h2) | ((uint32_t)__bfloat16_as_ushort(h3) << 16);
        uint32_t lA = (uint32_t)__bfloat16_as_ushort(__float2bfloat16_rn(l0)) |
                      ((uint32_t)__bfloat16_as_ushort(__float2bfloat16_rn(l1)) << 16);
        uint32_t lB = (uint32_t)__bfloat16_as_ushort(__float2bfloat16_rn(l2)) |
                      ((uint32_t)__bfloat16_as_ushort(__float2bfloat16_rn(l3)) << 16);
        uint32_t off = (uint32_t)(r * STR + kk) * 2;
        asm volatile("st.shared.v2.u32 [%0], {%1, %2};" :: "r"(dhi + off), "r"(hA), "r"(hB) : "memory");
        asm volatile("st.shared.v2.u32 [%0], {%1, %2};" :: "r"(dlo + off), "r"(lA), "r"(lB) : "memory");
    }
}

// MMA over one staged K=128 chunk. acc[mf][nf][4]; warp tile 32x64.
__device__ __forceinline__ void mma_chunk(float acc[2][8][4],
                                          uint32_t aHi, uint32_t aLo,
                                          uint32_t bHi, uint32_t bLo,
                                          int warp_m, int warp_n, int lane)
{
    const int q = lane >> 3, r = lane & 7;
    const uint32_t aOff = (uint32_t)((warp_m + (q & 1) * 8 + r) * STR + (q >> 1) * 8) * 2;
    const uint32_t bOff = (uint32_t)((warp_n + (q >> 1) * 8 + r) * STR + (q & 1) * 8) * 2;

    #pragma unroll
    for (int ks = 0; ks < 8; ++ks) {
        const uint32_t kb = ks * 32;
        uint32_t ah[2][4], al[2][4], bh[16], bl[16];
        ldsm4(ah[0], aHi + aOff + kb);
        ldsm4(ah[1], aHi + aOff + 16 * STR * 2 + kb);
        ldsm4(al[0], aLo + aOff + kb);
        ldsm4(al[1], aLo + aOff + 16 * STR * 2 + kb);
        #pragma unroll
        for (int n2 = 0; n2 < 4; ++n2) {
            ldsm4(bh + n2 * 4, bHi + bOff + n2 * 16 * STR * 2 + kb);
            ldsm4(bl + n2 * 4, bLo + bOff + n2 * 16 * STR * 2 + kb);
        }
        #pragma unroll
        for (int mf = 0; mf < 2; ++mf)
            #pragma unroll
            for (int nf = 0; nf < 8; ++nf) {
                mma_bf16(acc[mf][nf], ah[mf], bh + nf * 2);
                mma_bf16(acc[mf][nf], ah[mf], bl + nf * 2);
                mma_bf16(acc[mf][nf], al[mf], bh + nf * 2);
            }
    }
}

// Store acc into padded smem C staging. transpose=false: Cs[m][n]; true: Cs[n][m].
__device__ __forceinline__ void acc_to_smem(float* Cs, float acc[2][8][4],
                                            int warp_m, int warp_n, int lane, bool transpose)
{
    const int lr = lane >> 2, lc = (lane & 3) * 2;
    #pragma unroll
    for (int mf = 0; mf < 2; ++mf)
        #pragma unroll
        for (int nf = 0; nf < 8; ++nf) {
            int m = warp_m + mf * 16 + lr;
            int n = warp_n + nf * 8 + lc;
            float* a = acc[mf][nf];
            if (!transpose) {
                *(float2*)(Cs + m * CPAD + n)       = make_float2(a[0], a[1]);
                *(float2*)(Cs + (m + 8) * CPAD + n) = make_float2(a[2], a[3]);
            } else {
                Cs[n * CPAD + m]           = a[0];
                Cs[(n + 1) * CPAD + m]     = a[1];
                Cs[n * CPAD + m + 8]       = a[2];
                Cs[(n + 1) * CPAD + m + 8] = a[3];
            }
        }
}

// ---------------------------------------------------------------------------
// K0: featT[n][k] = feat[k][n]
// ---------------------------------------------------------------------------
__global__ __launch_bounds__(256)
void k_T(const float* __restrict__ feat)
{
    __shared__ float t[32][33];
    int n0 = blockIdx.x * 32, k0 = blockIdx.y * 32;
    int tx = threadIdx.x & 31, ty = threadIdx.x >> 5;
    #pragma unroll
    for (int j = 0; j < 4; ++j)
        t[ty + j * 8][tx] = feat[(size_t)(k0 + ty + j * 8) * N_TOK + n0 + tx];
    __syncthreads();
    #pragma unroll
    for (int j = 0; j < 4; ++j)
        g_featT[(size_t)(n0 + ty + j * 8) * CDIM + k0 + tx] = t[tx][ty + j * 8];
}

// ---------------------------------------------------------------------------
// K1: F = W_half @ feat + bias  (M=128, N=128 tokens, K=256 in 2 chunks)
//   half 0 -> g_FiT[n][p] (transposed), half 1 -> g_Fj[p][n]
// ---------------------------------------------------------------------------
__global__ __launch_bounds__(256)
void k_F(const float* __restrict__ Wi, const float* __restrict__ Wj,
         const float* __restrict__ bi, const float* __restrict__ bj)
{
    extern __shared__ __align__(16) char smem[];
    const uint32_t sb = smem_u32(smem);
    const uint32_t A_HI = 0, A_LO = TILE_B, B_HI = 2 * TILE_B, B_LO = 3 * TILE_B;
    float* Cs = (float*)smem;
    const int tid = threadIdx.x, lane = tid & 31, warp = tid >> 5;
    const int warp_m = (warp >> 1) * 32, warp_n = (warp & 1) * 64;
    const int n0 = blockIdx.x * 128;
    const int half = blockIdx.y;
    const float* W    = half ? Wj : Wi;
    const float* bias = half ? bj : bi;

    float acc[2][8][4] = {};

    #pragma unroll
    for (int c = 0; c < 2; ++c) {
        if (c) __syncthreads();            // protect tiles from restage
        stage<128>(sb + A_HI, sb + A_LO, W + c * 128, CDIM, tid);
        stage<128>(sb + B_HI, sb + B_LO, g_featT + (size_t)n0 * CDIM + c * 128, CDIM, tid);
        __syncthreads();
        mma_chunk(acc, sb + A_HI, sb + A_LO, sb + B_HI, sb + B_LO, warp_m, warp_n, lane);
    }

    // bias
    {
        const int lr = lane >> 2;
        #pragma unroll
        for (int mf = 0; mf < 2; ++mf) {
            float b0 = bias[warp_m + mf * 16 + lr];
            float b1 = bias[warp_m + mf * 16 + lr + 8];
            #pragma unroll
            for (int nf = 0; nf < 8; ++nf) {
                acc[mf][nf][0] += b0; acc[mf][nf][1] += b0;
                acc[mf][nf][2] += b1; acc[mf][nf][3] += b1;
            }
        }
    }

    __syncthreads();                       // everyone done reading tiles
    acc_to_smem(Cs, acc, warp_m, warp_n, lane, half == 0);
    __syncthreads();

    if (half == 0) {
        for (int i = tid; i < 128 * 32; i += 256) {
            int row = i >> 5, col = (i & 31) << 2;       // row = n, col = p
            float4 v = *(float4*)(Cs + row * CPAD + col);
            *(float4*)(g_FiT + (size_t)(n0 + row) * HDIM + col) = v;
        }
    } else {
        for (int i = tid; i < 128 * 32; i += 256) {
            int row = i >> 5, col = (i & 31) << 2;       // row = p, col = n
            float4 v = *(float4*)(Cs + row * CPAD + col);
            *(float4*)(g_Fj + (size_t)row * N_TOK + n0 + col) = v;
        }
    }
}

// ---------------------------------------------------------------------------
// K2: Gpart[z][p][q] = sum over token chunk z of Fj[p][n]*feat[q][n]
//   grid (81, 2): z chunk, q half. M=p(128), N=q(128), K=128.
// ---------------------------------------------------------------------------
__global__ __launch_bounds__(256)
void k_Gpart(const float* __restrict__ feat)
{
    extern __shared__ __align__(16) char smem[];
    const uint32_t sb = smem_u32(smem);
    const uint32_t A_HI = 0, A_LO = TILE_B, B_HI = 2 * TILE_B, B_LO = 3 * TILE_B;
    float* Cs = (float*)smem;
    const int tid = threadIdx.x, lane = tid & 31, warp = tid >> 5;
    const int warp_m = (warp >> 1) * 32, warp_n = (warp & 1) * 64;
    const int z = blockIdx.x, qh = blockIdx.y;

    float acc[2][8][4] = {};

    stage<128>(sb + A_HI, sb + A_LO, g_Fj + z * 128, N_TOK, tid);
    stage<128>(sb + B_HI, sb + B_LO, feat + (size_t)qh * 128 * N_TOK + z * 128, N_TOK, tid);
    __syncthreads();
    mma_chunk(acc, sb + A_HI, sb + A_LO, sb + B_HI, sb + B_LO, warp_m, warp_n, lane);

    __syncthreads();
    acc_to_smem(Cs, acc, warp_m, warp_n, lane, false);   // Cs[p][q]
    __syncthreads();

    float* outp = g_Gpart + (size_t)z * HDIM * CDIM + qh * 128;
    for (int i = tid; i < 128 * 32; i += 256) {
        int row = i >> 5, col = (i & 31) << 2;
        float4 v = *(float4*)(Cs + row * CPAD + col);
        *(float4*)(outp + (size_t)row * CDIM + col) = v;
    }
}

// ---------------------------------------------------------------------------
// K3: GT[q][p] = (1/N) * sum_z Gpart[z][p][q]
// ---------------------------------------------------------------------------
__global__ __launch_bounds__(256)
void k_R()
{
    int idx = blockIdx.x * 256 + threadIdx.x;     // p*256 + q
    float s = 0.f;
    #pragma unroll 3
    for (int c = 0; c < NCHUNK; ++c)
        s += g_Gpart[(size_t)c * HDIM * CDIM + idx];
    int p = idx >> 8, q = idx & 255;
    g_GT[(size_t)q * HDIM + p] = s * (1.0f / N_TOK);
}

// ---------------------------------------------------------------------------
// K4: out[q][n] = feat[q][n] + sum_p GT[q][p]*FiT[n][p]   (M=q 128/half, N=128, K=128)
// ---------------------------------------------------------------------------
__global__ __launch_bounds__(256)
void k_out(const float* __restrict__ feat, float* __restrict__ outp)
{
    extern __shared__ __align__(16) char smem[];
    const uint32_t sb = smem_u32(smem);
    const uint32_t A_HI = 0, A_LO = TILE_B, B_HI = 2 * TILE_B, B_LO = 3 * TILE_B;
    float* Cs = (float*)smem;
    const int tid = threadIdx.x, lane = tid & 31, warp = tid >> 5;
    const int warp_m = (warp >> 1) * 32, warp_n = (warp & 1) * 64;
    const int n0 = blockIdx.x * 128;
    const int half = blockIdx.y;

    float acc[2][8][4] = {};

    stage<128>(sb + A_HI, sb + A_LO, g_GT + (size_t)half * 128 * HDIM, HDIM, tid);
    stage<128>(sb + B_HI, sb + B_LO, g_FiT + (size_t)n0 * HDIM, HDIM, tid);
    __syncthreads();
    mma_chunk(acc, sb + A_HI, sb + A_LO, sb + B_HI, sb + B_LO, warp_m, warp_n, lane);

    __syncthreads();
    acc_to_smem(Cs, acc, warp_m, warp_n, lane, false);   // Cs[q][n]
    __syncthreads();

    for (int i = tid; i < 128 * 32; i += 256) {
        int row = i >> 5, col = (i & 31) << 2;
        size_t off = (size_t)(half * 128 + row) * N_TOK + n0 + col;
        float4 v = *(float4*)(Cs + row * CPAD + col);
        float4 f = *(const float4*)(feat + off);
        v.x += f.x; v.y += f.y; v.z += f.z; v.w += f.w;
        *(float4*)(outp + off) = v;
    }
}

// ---------------------------------------------------------------------------
extern "C" void kernel_launch(void* const* d_in, const int* in_sizes, int n_in,
                              void* d_out, int out_size)
{
    const float* feat = (const float*)d_in[0];
    const float* Wi   = (const float*)d_in[1];
    const float* bi   = (const float*)d_in[2];
    const float* Wj   = (const float*)d_in[3];
    const float* bj   = (const float*)d_in[4];
    float* outp = (float*)d_out;

    const int SMEM = 4 * TILE_B;   // 139,264 B
    static bool attr_set = false;
    if (!attr_set) {
        cudaFuncSetAttribute(k_F,     cudaFuncAttributeMaxDynamicSharedMemorySize, SMEM);
        cudaFuncSetAttribute(k_Gpart, cudaFuncAttributeMaxDynamicSharedMemorySize, SMEM);
        cudaFuncSetAttribute(k_out,   cudaFuncAttributeMaxDynamicSharedMemorySize, SMEM);
        attr_set = true;
    }

    k_T     <<<dim3(N_TOK / 32, CDIM / 32), 256>>>(feat);
    k_F     <<<dim3(81, 2), 256, SMEM>>>(Wi, Wj, bi, bj);
    k_Gpart <<<dim3(81, 2), 256, SMEM>>>(feat);
    k_R     <<<(HDIM * CDIM) / 256, 256>>>();
    k_out   <<<dim3(81, 2), 256, SMEM>>>(feat, outp);
}

// round 5
// speedup vs baseline: 1.6097x; 1.6097x over previous
#include <cuda_runtime.h>
#include <cuda_bf16.h>
#include <cstdint>

#define N_TOK 10368
#define CDIM  256
#define HDIM  128
#define NCHUNK 81
#define CPAD  132

// ---------------- scratch ----------------
__device__ float g_F   [(size_t)CDIM * N_TOK];           // rows 0-127 Fi[p][n], 128-255 Fj[p][n]
__device__ float g_Gpart[(size_t)NCHUNK * HDIM * CDIM];  // [z][p][q]
__device__ float g_G   [(size_t)HDIM * CDIM];            // G[p][q] = (1/N) sum_n Fj[p][n] feat[q][n]

// ---------------- helpers ----------------
__device__ __forceinline__ uint32_t smem_u32(const void* p) {
    uint32_t a;
    asm("{ .reg .u64 t; cvta.to.shared.u64 t, %1; cvt.u32.u64 %0, t; }" : "=r"(a) : "l"(p));
    return a;
}
__device__ __forceinline__ void ldsm4(uint32_t* r, uint32_t a) {
    asm volatile("ldmatrix.sync.aligned.m8n8.x4.shared.b16 {%0,%1,%2,%3}, [%4];"
                 : "=r"(r[0]), "=r"(r[1]), "=r"(r[2]), "=r"(r[3]) : "r"(a));
}
__device__ __forceinline__ void ldsm4t(uint32_t* r, uint32_t a) {
    asm volatile("ldmatrix.sync.aligned.m8n8.x4.trans.shared.b16 {%0,%1,%2,%3}, [%4];"
                 : "=r"(r[0]), "=r"(r[1]), "=r"(r[2]), "=r"(r[3]) : "r"(a));
}
__device__ __forceinline__ void mma_bf16(float* d, const uint32_t* a, const uint32_t* b) {
    asm volatile("mma.sync.aligned.m16n8k16.row.col.f32.bf16.bf16.f32 "
                 "{%0,%1,%2,%3}, {%4,%5,%6,%7}, {%8,%9}, {%0,%1,%2,%3};"
                 : "+f"(d[0]), "+f"(d[1]), "+f"(d[2]), "+f"(d[3])
                 : "r"(a[0]), "r"(a[1]), "r"(a[2]), "r"(a[3]), "r"(b[0]), "r"(b[1]));
}

// Stage a [ROWS x KW] fp32 tile (leading dim ld) into hi/lo bf16 padded tiles.
template<int ROWS, int KW>
__device__ __forceinline__ void stage(uint32_t dhi, uint32_t dlo,
                                      const float* __restrict__ src, int ld, int tid)
{
    constexpr int PSTR = KW + 8;
    constexpr int RV = KW / 4;
    for (int i = tid; i < ROWS * RV; i += 256) {
        int r = i / RV, kk = (i % RV) * 4;
        float4 v = *(const float4*)(src + (size_t)r * ld + kk);
        __nv_bfloat16 h0 = __float2bfloat16_rn(v.x), h1 = __float2bfloat16_rn(v.y),
                      h2 = __float2bfloat16_rn(v.z), h3 = __float2bfloat16_rn(v.w);
        float l0 = v.x - __bfloat162float(h0), l1 = v.y - __bfloat162float(h1),
              l2 = v.z - __bfloat162float(h2), l3 = v.w - __bfloat162float(h3);
        uint32_t hA = (uint32_t)__bfloat16_as_ushort(h0) | ((uint32_t)__bfloat16_as_ushort(h1) << 16);
        uint32_t hB = (uint32_t)__bfloat16_as_ushort(h2) | ((uint32_t)__bfloat16_as_ushort(h3) << 16);
        uint32_t lA = (uint32_t)__bfloat16_as_ushort(__float2bfloat16_rn(l0)) |
                      ((uint32_t)__bfloat16_as_ushort(__float2bfloat16_rn(l1)) << 16);
        uint32_t lB = (uint32_t)__bfloat16_as_ushort(__float2bfloat16_rn(l2)) |
                      ((uint32_t)__bfloat16_as_ushort(__float2bfloat16_rn(l3)) << 16);
        uint32_t off = (uint32_t)(r * PSTR + kk) * 2;
        asm volatile("st.shared.v2.u32 [%0], {%1, %2};" :: "r"(dhi + off), "r"(hA), "r"(hB) : "memory");
        asm volatile("st.shared.v2.u32 [%0], {%1, %2};" :: "r"(dlo + off), "r"(lA), "r"(lB) : "memory");
    }
}

// MMA over one staged K=64 chunk (4 k16 steps), warp tile 32x64.
// AT/BT: operand stored [K][dim] -> use trans ldmatrix. ASTR/BSTR: padded rows.
template<bool AT, bool BT, int ASTR, int BSTR>
__device__ __forceinline__ void mma_chunk(float acc[2][8][4],
                                          uint32_t aHi, uint32_t aLo,
                                          uint32_t bHi, uint32_t bLo,
                                          int warp_m, int warp_n, int lane)
{
    const int q = lane >> 3, rr = lane & 7;
    uint32_t aBase, aStep, aM16, bBase, bStep, bN16;
    if (!AT) { aBase = (uint32_t)((warp_m + (q & 1) * 8 + rr) * ASTR + (q >> 1) * 8) * 2;
               aStep = 32; aM16 = 16 * ASTR * 2; }
    else     { aBase = (uint32_t)(((q >> 1) * 8 + rr) * ASTR + warp_m + (q & 1) * 8) * 2;
               aStep = 16 * ASTR * 2; aM16 = 32; }
    if (!BT) { bBase = (uint32_t)((warp_n + (q >> 1) * 8 + rr) * BSTR + (q & 1) * 8) * 2;
               bStep = 32; bN16 = 16 * BSTR * 2; }
    else     { bBase = (uint32_t)(((q & 1) * 8 + rr) * BSTR + warp_n + (q >> 1) * 8) * 2;
               bStep = 16 * BSTR * 2; bN16 = 32; }

    #pragma unroll
    for (int ks = 0; ks < 4; ++ks) {
        uint32_t ah[2][4], al[2][4], bh[16], bl[16];
        uint32_t aA = aBase + ks * aStep, bA = bBase + ks * bStep;
        if (AT) { ldsm4t(ah[0], aHi + aA); ldsm4t(ah[1], aHi + aA + aM16);
                  ldsm4t(al[0], aLo + aA); ldsm4t(al[1], aLo + aA + aM16); }
        else    { ldsm4 (ah[0], aHi + aA); ldsm4 (ah[1], aHi + aA + aM16);
                  ldsm4 (al[0], aLo + aA); ldsm4 (al[1], aLo + aA + aM16); }
        #pragma unroll
        for (int n2 = 0; n2 < 4; ++n2) {
            if (BT) { ldsm4t(bh + n2 * 4, bHi + bA + n2 * bN16);
                      ldsm4t(bl + n2 * 4, bLo + bA + n2 * bN16); }
            else    { ldsm4 (bh + n2 * 4, bHi + bA + n2 * bN16);
                      ldsm4 (bl + n2 * 4, bLo + bA + n2 * bN16); }
        }
        #pragma unroll
        for (int mf = 0; mf < 2; ++mf)
            #pragma unroll
            for (int nf = 0; nf < 8; ++nf) {
                mma_bf16(acc[mf][nf], ah[mf], bh + nf * 2);
                mma_bf16(acc[mf][nf], ah[mf], bl + nf * 2);
                mma_bf16(acc[mf][nf], al[mf], bh + nf * 2);
            }
    }
}

__device__ __forceinline__ void acc_to_smem(float* Cs, float acc[2][8][4],
                                            int warp_m, int warp_n, int lane)
{
    const int lr = lane >> 2, lc = (lane & 3) * 2;
    #pragma unroll
    for (int mf = 0; mf < 2; ++mf)
        #pragma unroll
        for (int nf = 0; nf < 8; ++nf) {
            int m = warp_m + mf * 16 + lr;
            int n = warp_n + nf * 8 + lc;
            float* a = acc[mf][nf];
            *(float2*)(Cs + m * CPAD + n)       = make_float2(a[0], a[1]);
            *(float2*)(Cs + (m + 8) * CPAD + n) = make_float2(a[2], a[3]);
        }
}

// smem budget (shared by all GEMM kernels)
#define SMEM_BYTES 73728

// ---------------------------------------------------------------------------
// K1: F[p][n] = W_half @ feat + bias ; M=128 (p), N=128 tokens, K=256 (4x64)
//   A = W (row-major K) non-trans ; B = feat[k][n] -> trans
// ---------------------------------------------------------------------------
__global__ __launch_bounds__(256, 2)
void k_F(const float* __restrict__ feat,
         const float* __restrict__ Wi, const float* __restrict__ Wj,
         const float* __restrict__ bi, const float* __restrict__ bj)
{
    extern __shared__ __align__(16) char smem[];
    const uint32_t sb = smem_u32(smem);
    const uint32_t A_HI = 0, A_LO = 18432, B_HI = 36864, B_LO = 54272;   // A:128x72, B:64x136
    float* Cs = (float*)smem;
    const int tid = threadIdx.x, lane = tid & 31, warp = tid >> 5;
    const int warp_m = (warp >> 1) * 32, warp_n = (warp & 1) * 64;
    const int n0 = blockIdx.x * 128, half = blockIdx.y;
    const float* W    = half ? Wj : Wi;
    const float* bias = half ? bj : bi;

    float acc[2][8][4] = {};

    #pragma unroll
    for (int c = 0; c < 4; ++c) {
        if (c) __syncthreads();
        stage<128, 64>(sb + A_HI, sb + A_LO, W + c * 64, CDIM, tid);
        stage<64, 128>(sb + B_HI, sb + B_LO, feat + (size_t)(c * 64) * N_TOK + n0, N_TOK, tid);
        __syncthreads();
        mma_chunk<false, true, 72, 136>(acc, sb + A_HI, sb + A_LO, sb + B_HI, sb + B_LO,
                                        warp_m, warp_n, lane);
    }

    {   // bias
        const int lr = lane >> 2;
        #pragma unroll
        for (int mf = 0; mf < 2; ++mf) {
            float b0 = bias[warp_m + mf * 16 + lr];
            float b1 = bias[warp_m + mf * 16 + lr + 8];
            #pragma unroll
            for (int nf = 0; nf < 8; ++nf) {
                acc[mf][nf][0] += b0; acc[mf][nf][1] += b0;
                acc[mf][nf][2] += b1; acc[mf][nf][3] += b1;
            }
        }
    }

    __syncthreads();
    acc_to_smem(Cs, acc, warp_m, warp_n, lane);
    __syncthreads();
    for (int i = tid; i < 128 * 32; i += 256) {
        int row = i >> 5, col = (i & 31) << 2;
        float4 v = *(float4*)(Cs + row * CPAD + col);
        *(float4*)(g_F + (size_t)(half * 128 + row) * N_TOK + n0 + col) = v;
    }
}

// ---------------------------------------------------------------------------
// K2: Gpart[z][p][q] over token chunk z ; M=p(128), N=q(128), K=128 (2x64)
//   A = Fj[p][n] non-trans ; B = feat[q][n] non-trans
// ---------------------------------------------------------------------------
__global__ __launch_bounds__(256, 2)
void k_Gpart(const float* __restrict__ feat)
{
    extern __shared__ __align__(16) char smem[];
    const uint32_t sb = smem_u32(smem);
    const uint32_t A_HI = 0, A_LO = 18432, B_HI = 36864, B_LO = 55296;   // both 128x72
    float* Cs = (float*)smem;
    const int tid = threadIdx.x, lane = tid & 31, warp = tid >> 5;
    const int warp_m = (warp >> 1) * 32, warp_n = (warp & 1) * 64;
    const int z = blockIdx.x, qh = blockIdx.y;
    const float* Fj = g_F + (size_t)HDIM * N_TOK;

    float acc[2][8][4] = {};

    #pragma unroll
    for (int c = 0; c < 2; ++c) {
        if (c) __syncthreads();
        stage<128, 64>(sb + A_HI, sb + A_LO, Fj + z * 128 + c * 64, N_TOK, tid);
        stage<128, 64>(sb + B_HI, sb + B_LO,
                       feat + (size_t)qh * 128 * N_TOK + z * 128 + c * 64, N_TOK, tid);
        __syncthreads();
        mma_chunk<false, false, 72, 72>(acc, sb + A_HI, sb + A_LO, sb + B_HI, sb + B_LO,
                                        warp_m, warp_n, lane);
    }

    __syncthreads();
    acc_to_smem(Cs, acc, warp_m, warp_n, lane);
    __syncthreads();
    float* outp = g_Gpart + (size_t)z * HDIM * CDIM + qh * 128;
    for (int i = tid; i < 128 * 32; i += 256) {
        int row = i >> 5, col = (i & 31) << 2;
        float4 v = *(float4*)(Cs + row * CPAD + col);
        *(float4*)(outp + (size_t)row * CDIM + col) = v;
    }
}

// ---------------------------------------------------------------------------
// K3: G[p][q] = (1/N) * sum_z Gpart[z][p][q]  (coalesced float4, 3-way MLP)
// ---------------------------------------------------------------------------
__global__ __launch_bounds__(256)
void k_R()
{
    const int t = blockIdx.x * 256 + threadIdx.x;    // 0..8191 float4 slots
    const float4* gp = (const float4*)g_Gpart;
    float4 a0 = {0,0,0,0}, a1 = {0,0,0,0}, a2 = {0,0,0,0};
    #pragma unroll 3
    for (int z = 0; z < NCHUNK; z += 3) {
        float4 v0 = gp[(size_t)z * 8192 + t];
        float4 v1 = gp[(size_t)(z + 1) * 8192 + t];
        float4 v2 = gp[(size_t)(z + 2) * 8192 + t];
        a0.x += v0.x; a0.y += v0.y; a0.z += v0.z; a0.w += v0.w;
        a1.x += v1.x; a1.y += v1.y; a1.z += v1.z; a1.w += v1.w;
        a2.x += v2.x; a2.y += v2.y; a2.z += v2.z; a2.w += v2.w;
    }
    const float s = 1.0f / N_TOK;
    float4 r = make_float4((a0.x + a1.x + a2.x) * s, (a0.y + a1.y + a2.y) * s,
                           (a0.z + a1.z + a2.z) * s, (a0.w + a1.w + a2.w) * s);
    ((float4*)g_G)[t] = r;
}

// ---------------------------------------------------------------------------
// K4: out[q][n] = feat[q][n] + sum_p G[p][q] * Fi[p][n] ; M=q(128/half), K=128 (2x64)
//   A = G[p][q] -> trans ; B = Fi[p][n] -> trans
// ---------------------------------------------------------------------------
__global__ __launch_bounds__(256, 2)
void k_out(const float* __restrict__ feat, float* __restrict__ outp)
{
    extern __shared__ __align__(16) char smem[];
    const uint32_t sb = smem_u32(smem);
    const uint32_t A_HI = 0, A_LO = 17408, B_HI = 34816, B_LO = 52224;   // both 64x136
    float* Cs = (float*)smem;
    const int tid = threadIdx.x, lane = tid & 31, warp = tid >> 5;
    const int warp_m = (warp >> 1) * 32, warp_n = (warp & 1) * 64;
    const int n0 = blockIdx.x * 128, half = blockIdx.y;

    float acc[2][8][4] = {};

    #pragma unroll
    for (int c = 0; c < 2; ++c) {
        if (c) __syncthreads();
        stage<64, 128>(sb + A_HI, sb + A_LO, g_G + (size_t)(c * 64) * CDIM + half * 128, CDIM, tid);
        stage<64, 128>(sb + B_HI, sb + B_LO, g_F + (size_t)(c * 64) * N_TOK + n0, N_TOK, tid);
        __syncthreads();
        mma_chunk<true, true, 136, 136>(acc, sb + A_HI, sb + A_LO, sb + B_HI, sb + B_LO,
                                        warp_m, warp_n, lane);
    }

    __syncthreads();
    acc_to_smem(Cs, acc, warp_m, warp_n, lane);
    __syncthreads();
    for (int i = tid; i < 128 * 32; i += 256) {
        int row = i >> 5, col = (i & 31) << 2;
        size_t off = (size_t)(half * 128 + row) * N_TOK + n0 + col;
        float4 v = *(float4*)(Cs + row * CPAD + col);
        float4 f = *(const float4*)(feat + off);
        v.x += f.x; v.y += f.y; v.z += f.z; v.w += f.w;
        *(float4*)(outp + off) = v;
    }
}

// ---------------------------------------------------------------------------
extern "C" void kernel_launch(void* const* d_in, const int* in_sizes, int n_in,
                              void* d_out, int out_size)
{
    const float* feat = (const float*)d_in[0];
    const float* Wi   = (const float*)d_in[1];
    const float* bi   = (const float*)d_in[2];
    const float* Wj   = (const float*)d_in[3];
    const float* bj   = (const float*)d_in[4];
    float* outp = (float*)d_out;

    static bool attr_set = false;
    if (!attr_set) {
        cudaFuncSetAttribute(k_F,     cudaFuncAttributeMaxDynamicSharedMemorySize, SMEM_BYTES);
        cudaFuncSetAttribute(k_Gpart, cudaFuncAttributeMaxDynamicSharedMemorySize, SMEM_BYTES);
        cudaFuncSetAttribute(k_out,   cudaFuncAttributeMaxDynamicSharedMemorySize, SMEM_BYTES);
        attr_set = true;
    }

    k_F     <<<dim3(81, 2), 256, SMEM_BYTES>>>(feat, Wi, Wj, bi, bj);
    k_Gpart <<<dim3(81, 2), 256, SMEM_BYTES>>>(feat);
    k_R     <<<32, 256>>>();
    k_out   <<<dim3(81, 2), 256, SMEM_BYTES>>>(feat, outp);
}